// round 7
// baseline (speedup 1.0000x reference)
#include <cuda_runtime.h>

#define FULLMASK 0xffffffffu

static __device__ __forceinline__ float fixv(float p) {
    return (p == -1.0f) ? 0.0f : p;
}

static __device__ __forceinline__ float tanh_fast(float x) {
    float y;
    asm("tanh.approx.f32 %0, %1;" : "=f"(y) : "f"(x));
    return y;
}

// One CTA per batch image, 1024 threads, 2x2 pixel tile per thread.
// Warp w owns image rows 2w,2w+1; lane j owns cols 2j,2j+1.
//
// TEMPORAL BLOCKING: each barrier round advances TWO time steps.
// Round: store own h^k rows -> barrier -> load 2-row h^k halo (rows
// 2w-2..2w+3) -> compute u^{k+1} on rows 2w-1..2w+2 (halo rows redundantly,
// using preloaded halo cs/sw) -> local h^{k+1} via shuffles -> u^{k+2} on own
// rows. 6 rounds = 12 iterations, 6 barriers instead of 12.
__global__ __launch_bounds__(1024, 1)
void prop_kernel(const float* __restrict__ X,
                 const float* __restrict__ pred,
                 const float* __restrict__ w,
                 const float* __restrict__ a,
                 const float* __restrict__ bias,
                 const float* __restrict__ scalar,
                 float* __restrict__ out)
{
    constexpr int NS = 64;          // image side
    constexpr int HH = NS * NS;     // 4096 pixels
    constexpr int SROWS = 68;       // +2 zero halo rows EACH side (idx = row+2)
    constexpr int ROUNDS = 6;       // 2 steps per round

    __shared__ float Hs[2][SROWS * NS];   // h^k grids, double buffered

    const int b    = blockIdx.x;
    const int t    = threadIdx.x;
    const int wrp  = t >> 5;        // rows 2w, 2w+1
    const int lane = t & 31;        // cols 2j, 2j+1

    // Zero the 2-row halos (idx 0,1,66,67) in both buffers, once.
    if (t < NS) {
        Hs[0][t] = 0.f;  Hs[0][NS + t] = 0.f;
        Hs[0][66 * NS + t] = 0.f;  Hs[0][67 * NS + t] = 0.f;
        Hs[1][t] = 0.f;  Hs[1][NS + t] = 0.f;
        Hs[1][66 * NS + t] = 0.f;  Hs[1][67 * NS + t] = 0.f;
    }

    const float s = scalar[0];
    const int rT = wrp * 2;
    const int c  = lane * 2;
    const int gT = b * HH + rT * NS + c;    // global, top row
    const int gB = gT + NS;                 // bottom row
    const int pT = rT * NS + c;
    const int pB = pT + NS;

    // Own-row loads
    float2 prT = *(const float2*)(pred + gT);
    float2 prB = *(const float2*)(pred + gB);
    float2 xT  = *(const float2*)(X    + gT);
    float2 xB  = *(const float2*)(X    + gB);
    float2 wT  = *(const float2*)(w    + pT);
    float2 wB  = *(const float2*)(w    + pB);
    float2 aT  = *(const float2*)(a    + pT);
    float2 aB  = *(const float2*)(a    + pB);
    float2 bT  = *(const float2*)(bias + pT);
    float2 bB  = *(const float2*)(bias + pB);

    float4 cs, sw;   // x,y = top row; z,w = bottom row
    cs.x = s * (fixv(prT.x) + bT.x + aT.x * xT.x);
    cs.y = s * (fixv(prT.y) + bT.y + aT.y * xT.y);
    cs.z = s * (fixv(prB.x) + bB.x + aB.x * xB.x);
    cs.w = s * (fixv(prB.y) + bB.y + aB.y * xB.y);
    sw.x = s * wT.x;  sw.y = s * wT.y;  sw.z = s * wB.x;  sw.w = s * wB.y;

    // Halo-row constants (row 2w-1 above, row 2w+2 below); zero at image edge
    // so the redundant u^{k+1} there evaluates to tanh(0)=0 -> h^{k+1}=0.
    float2 csU = make_float2(0.f, 0.f), swU = csU;
    float2 csD = csU, swD = csU;
    if (wrp > 0) {
        const int g = gT - NS, p = pT - NS;
        float2 pr = *(const float2*)(pred + g);
        float2 xx = *(const float2*)(X    + g);
        float2 ww = *(const float2*)(w    + p);
        float2 aa = *(const float2*)(a    + p);
        float2 bb = *(const float2*)(bias + p);
        csU.x = s * (fixv(pr.x) + bb.x + aa.x * xx.x);
        csU.y = s * (fixv(pr.y) + bb.y + aa.y * xx.y);
        swU.x = s * ww.x;  swU.y = s * ww.y;
    }
    if (wrp < 31) {
        const int g = gB + NS, p = pB + NS;
        float2 pr = *(const float2*)(pred + g);
        float2 xx = *(const float2*)(X    + g);
        float2 ww = *(const float2*)(w    + p);
        float2 aa = *(const float2*)(a    + p);
        float2 bb = *(const float2*)(bias + p);
        csD.x = s * (fixv(pr.x) + bb.x + aa.x * xx.x);
        csD.y = s * (fixv(pr.y) + bb.y + aa.y * xx.y);
        swD.x = s * ww.x;  swD.y = s * ww.y;
    }

    // smem indices: image row r -> halo idx r+2
    const int iST = (rT + 2) * NS + c;   // own top h-row (bottom at +NS)
    const int iM2 =  rT      * NS + c;   // h row 2w-2 (then +NS, +4NS, +5NS)

    __syncthreads();

    float4 u = make_float4(prT.x, prT.y, prB.x, prB.y);   // u^0 = pred

    // horizontal 3-sum of a 2-col row fragment held across the warp
    auto hsum = [&](float2 v) -> float2 {
        float sp = v.x + v.y;
        float l  = __shfl_up_sync  (FULLMASK, v.y, 1);
        float r  = __shfl_down_sync(FULLMASK, v.x, 1);
        if (lane == 0)  l = 0.f;
        if (lane == 31) r = 0.f;
        return make_float2(l + sp, sp + r);
    };

    #pragma unroll
    for (int rd = 0; rd < ROUNDS; ++rd) {
        float* __restrict__ Hc = Hs[rd & 1];

        // ---- h^k of own rows ----
        float2 hT = hsum(make_float2(u.x, u.y));
        float2 hB = hsum(make_float2(u.z, u.w));

        *(float2*)&Hc[iST]      = hT;
        *(float2*)&Hc[iST + NS] = hB;
        __syncthreads();

        // ---- 2-row h^k halo ----
        const float2 hm2 = *(const float2*)&Hc[iM2];            // row 2w-2
        const float2 hm1 = *(const float2*)&Hc[iM2 + NS];       // row 2w-1
        const float2 hp2 = *(const float2*)&Hc[iM2 + 4 * NS];   // row 2w+2
        const float2 hp3 = *(const float2*)&Hc[iM2 + 5 * NS];   // row 2w+3

        // ---- u^{k+1} on rows 2w-1 .. 2w+2 ----
        float2 vA  = make_float2(hm1.x + hT.x, hm1.y + hT.y);   // hm1+hT
        float2 vTB = make_float2(hT.x + hB.x,  hT.y + hB.y);    // hT+hB

        float2 uU, uT1, uB1, uD;
        uU.x  = tanh_fast(fmaf(swU.x, hm2.x + vA.x, csU.x));
        uU.y  = tanh_fast(fmaf(swU.y, hm2.y + vA.y, csU.y));
        uT1.x = tanh_fast(fmaf(sw.x,  vA.x + hB.x,  cs.x));
        uT1.y = tanh_fast(fmaf(sw.y,  vA.y + hB.y,  cs.y));
        uB1.x = tanh_fast(fmaf(sw.z,  vTB.x + hp2.x, cs.z));
        uB1.y = tanh_fast(fmaf(sw.w,  vTB.y + hp2.y, cs.w));
        uD.x  = tanh_fast(fmaf(swD.x, hB.x + hp2.x + hp3.x, csD.x));
        uD.y  = tanh_fast(fmaf(swD.y, hB.y + hp2.y + hp3.y, csD.y));

        // ---- h^{k+1} on those rows ----
        float2 h1U = hsum(uU);
        float2 h1T = hsum(uT1);
        float2 h1B = hsum(uB1);
        float2 h1D = hsum(uD);

        // ---- u^{k+2} on own rows ----
        float2 m = make_float2(h1T.x + h1B.x, h1T.y + h1B.y);
        u.x = tanh_fast(fmaf(sw.x, h1U.x + m.x, cs.x));
        u.y = tanh_fast(fmaf(sw.y, h1U.y + m.y, cs.y));
        u.z = tanh_fast(fmaf(sw.z, m.x + h1D.x, cs.z));
        u.w = tanh_fast(fmaf(sw.w, m.y + h1D.y, cs.w));
    }

    *(float2*)(out + gT) = make_float2(u.x, u.y);
    *(float2*)(out + gB) = make_float2(u.z, u.w);
}

extern "C" void kernel_launch(void* const* d_in, const int* in_sizes, int n_in,
                              void* d_out, int out_size) {
    const float* X      = (const float*)d_in[0];
    const float* pred   = (const float*)d_in[1];
    const float* w      = (const float*)d_in[2];
    const float* a      = (const float*)d_in[3];
    const float* bias   = (const float*)d_in[4];
    const float* scalar = (const float*)d_in[5];
    float* out = (float*)d_out;

    const int B = in_sizes[0] / 4096;   // batch = 128
    prop_kernel<<<B, 1024>>>(X, pred, w, a, bias, scalar, out);
}

// round 8
// speedup vs baseline: 1.2694x; 1.2694x over previous
#include <cuda_runtime.h>

#define FULLMASK 0xffffffffu

static __device__ __forceinline__ float fixv(float p) {
    return (p == -1.0f) ? 0.0f : p;
}

static __device__ __forceinline__ float tanh_fast(float x) {
    float y;
    asm("tanh.approx.f32 %0, %1;" : "=f"(y) : "f"(x));
    return y;
}

// One CTA per batch image, 512 threads, 8 pixels/thread.
// Warp w (of 16) owns TWO distant row-pair bands: rows {2w,2w+1} and
// {2w+32,2w+33}. Lane j owns cols 2j,2j+1 in each band. The two bands give
// every thread two independent dependency chains (2x ILP), and the barrier
// convoy shrinks from 32 to 16 warp arrivals — with identical total work,
// crossbar traffic, and MUFU load per SM as the R6 kernel.
__global__ __launch_bounds__(512, 1)
void prop_kernel(const float* __restrict__ X,
                 const float* __restrict__ pred,
                 const float* __restrict__ w,
                 const float* __restrict__ a,
                 const float* __restrict__ bias,
                 const float* __restrict__ scalar,
                 float* __restrict__ out)
{
    constexpr int NS = 64;          // image side
    constexpr int HH = NS * NS;     // 4096 pixels
    constexpr int SROWS = 66;       // +1 zero halo row each side (idx = row+1)
    constexpr int ITERS = 12;

    __shared__ float Hs[2][SROWS * NS];   // horizontal 3-sums, double buffered

    const int b    = blockIdx.x;
    const int t    = threadIdx.x;
    const int wrp  = t >> 5;        // 0..15
    const int lane = t & 31;        // cols 2j, 2j+1

    // Zero halo rows (halo idx 0 and 65) in both buffers, once.
    if (t < NS) {
        Hs[0][t] = 0.f;            Hs[1][t] = 0.f;
        Hs[0][65 * NS + t] = 0.f;  Hs[1][65 * NS + t] = 0.f;
    }

    const float s = scalar[0];
    const int c = lane * 2;

    // Band row-pair indices
    const int rA = wrp * 2;          // band A top row
    const int rB = rA + 32;          // band B top row

    // ---- per-band parameter setup (cs = s*(u_fix+bias+a*X), sw = s*w) ----
    const int gA = b * HH + rA * NS + c;   // band A top-row global idx
    const int gB = b * HH + rB * NS + c;   // band B top-row global idx
    const int pA = rA * NS + c;
    const int pB = rB * NS + c;

    float2 prA0 = *(const float2*)(pred + gA);
    float2 prA1 = *(const float2*)(pred + gA + NS);
    float2 prB0 = *(const float2*)(pred + gB);
    float2 prB1 = *(const float2*)(pred + gB + NS);

    float2 xA0 = *(const float2*)(X + gA);
    float2 xA1 = *(const float2*)(X + gA + NS);
    float2 xB0 = *(const float2*)(X + gB);
    float2 xB1 = *(const float2*)(X + gB + NS);

    float2 wA0 = *(const float2*)(w + pA);
    float2 wA1 = *(const float2*)(w + pA + NS);
    float2 wB0 = *(const float2*)(w + pB);
    float2 wB1 = *(const float2*)(w + pB + NS);

    float2 aA0 = *(const float2*)(a + pA);
    float2 aA1 = *(const float2*)(a + pA + NS);
    float2 aB0 = *(const float2*)(a + pB);
    float2 aB1 = *(const float2*)(a + pB + NS);

    float2 bA0 = *(const float2*)(bias + pA);
    float2 bA1 = *(const float2*)(bias + pA + NS);
    float2 bB0 = *(const float2*)(bias + pB);
    float2 bB1 = *(const float2*)(bias + pB + NS);

    float4 csA, swA, csB, swB;   // x,y = top row; z,w = bottom row
    csA.x = s * (fixv(prA0.x) + bA0.x + aA0.x * xA0.x);
    csA.y = s * (fixv(prA0.y) + bA0.y + aA0.y * xA0.y);
    csA.z = s * (fixv(prA1.x) + bA1.x + aA1.x * xA1.x);
    csA.w = s * (fixv(prA1.y) + bA1.y + aA1.y * xA1.y);
    csB.x = s * (fixv(prB0.x) + bB0.x + aB0.x * xB0.x);
    csB.y = s * (fixv(prB0.y) + bB0.y + aB0.y * xB0.y);
    csB.z = s * (fixv(prB1.x) + bB1.x + aB1.x * xB1.x);
    csB.w = s * (fixv(prB1.y) + bB1.y + aB1.y * xB1.y);
    swA.x = s * wA0.x;  swA.y = s * wA0.y;  swA.z = s * wA1.x;  swA.w = s * wA1.y;
    swB.x = s * wB0.x;  swB.y = s * wB0.y;  swB.z = s * wB1.x;  swB.w = s * wB1.y;

    // smem indices (image row r -> halo idx r+1)
    const int stA = (rA + 1) * NS + c;   // band A: own top h-row (bottom +NS)
    const int stB = (rB + 1) * NS + c;   // band B
    const int luA =  rA      * NS + c;   // band A halo above (down at +3NS)
    const int luB =  rB      * NS + c;   // band B

    __syncthreads();

    float4 uA = make_float4(prA0.x, prA0.y, prA1.x, prA1.y);   // u_0 = pred
    float4 uB = make_float4(prB0.x, prB0.y, prB1.x, prB1.y);

    #pragma unroll
    for (int it = 0; it < ITERS; ++it) {
        float* __restrict__ Hc = Hs[it & 1];

        // ---- horizontal 3-sums, both bands interleaved ----
        float sAT = uA.x + uA.y,  sAB = uA.z + uA.w;
        float sBT = uB.x + uB.y,  sBB = uB.z + uB.w;

        float lAT = __shfl_up_sync  (FULLMASK, uA.y, 1);
        float rAT = __shfl_down_sync(FULLMASK, uA.x, 1);
        float lAB = __shfl_up_sync  (FULLMASK, uA.w, 1);
        float rAB = __shfl_down_sync(FULLMASK, uA.z, 1);
        float lBT = __shfl_up_sync  (FULLMASK, uB.y, 1);
        float rBT = __shfl_down_sync(FULLMASK, uB.x, 1);
        float lBB = __shfl_up_sync  (FULLMASK, uB.w, 1);
        float rBB = __shfl_down_sync(FULLMASK, uB.z, 1);
        if (lane == 0)  { lAT = 0.f; lAB = 0.f; lBT = 0.f; lBB = 0.f; }
        if (lane == 31) { rAT = 0.f; rAB = 0.f; rBT = 0.f; rBB = 0.f; }

        float hAT0 = lAT + sAT,  hAT1 = sAT + rAT;
        float hAB0 = lAB + sAB,  hAB1 = sAB + rAB;
        float hBT0 = lBT + sBT,  hBT1 = sBT + rBT;
        float hBB0 = lBB + sBB,  hBB1 = sBB + rBB;

        *(float2*)&Hc[stA]      = make_float2(hAT0, hAT1);
        *(float2*)&Hc[stA + NS] = make_float2(hAB0, hAB1);
        *(float2*)&Hc[stB]      = make_float2(hBT0, hBT1);
        *(float2*)&Hc[stB + NS] = make_float2(hBB0, hBB1);

        // vertical mid-sums from own registers (independent of the barrier)
        float mA0 = hAT0 + hAB0,  mA1 = hAT1 + hAB1;
        float mB0 = hBT0 + hBB0,  mB1 = hBT1 + hBB1;

        __syncthreads();

        // ---- outer halo h-rows, both bands ----
        const float2 hUA = *(const float2*)&Hc[luA];
        const float2 hDA = *(const float2*)&Hc[luA + 3 * NS];
        const float2 hUB = *(const float2*)&Hc[luB];
        const float2 hDB = *(const float2*)&Hc[luB + 3 * NS];

        // ---- u_new = tanh(cs + sw * vsum), 8 independent lanes of work ----
        uA.x = tanh_fast(fmaf(swA.x, hUA.x + mA0, csA.x));
        uA.y = tanh_fast(fmaf(swA.y, hUA.y + mA1, csA.y));
        uA.z = tanh_fast(fmaf(swA.z, mA0 + hDA.x, csA.z));
        uA.w = tanh_fast(fmaf(swA.w, mA1 + hDA.y, csA.w));
        uB.x = tanh_fast(fmaf(swB.x, hUB.x + mB0, csB.x));
        uB.y = tanh_fast(fmaf(swB.y, hUB.y + mB1, csB.y));
        uB.z = tanh_fast(fmaf(swB.z, mB0 + hDB.x, csB.z));
        uB.w = tanh_fast(fmaf(swB.w, mB1 + hDB.y, csB.w));
    }

    *(float2*)(out + gA)      = make_float2(uA.x, uA.y);
    *(float2*)(out + gA + NS) = make_float2(uA.z, uA.w);
    *(float2*)(out + gB)      = make_float2(uB.x, uB.y);
    *(float2*)(out + gB + NS) = make_float2(uB.z, uB.w);
}

extern "C" void kernel_launch(void* const* d_in, const int* in_sizes, int n_in,
                              void* d_out, int out_size) {
    const float* X      = (const float*)d_in[0];
    const float* pred   = (const float*)d_in[1];
    const float* w      = (const float*)d_in[2];
    const float* a      = (const float*)d_in[3];
    const float* bias   = (const float*)d_in[4];
    const float* scalar = (const float*)d_in[5];
    float* out = (float*)d_out;

    const int B = in_sizes[0] / 4096;   // batch = 128
    prop_kernel<<<B, 512>>>(X, pred, w, a, bias, scalar, out);
}